// round 14
// baseline (speedup 1.0000x reference)
#include <cuda_runtime.h>
#include <math.h>

#define Bx 2
#define Lx 2048
#define Cx 1024
#define Hx 16
#define Dx 64
#define MTOT (Bx*Lx)          // 4096

__device__ float g_qkv[MTOT * 3 * Cx];                      // 50 MB
__device__ float g_attn[MTOT * Cx];                         // 16 MB

// ===========================================================================
// SGEMM 128x128, k-chunks of 16, register-staged double buffer, 1 sync/chunk.
// [round-12 measured best: out 228 us] — reverted verbatim.
// ===========================================================================
__device__ __forceinline__ void sgemm_core(const float* __restrict__ A,
                                           const float* __restrict__ Bw,
                                           const float* __restrict__ bias,
                                           float* __restrict__ Cc,
                                           int M, int N, int K)
{
    __shared__ float As[2][16][128];
    __shared__ float Bs[2][16][128];

    const int tid = threadIdx.x;
    const int m0 = blockIdx.y * 128;
    const int n0 = blockIdx.x * 128;
    const int tr = tid >> 4;
    const int tc = tid & 15;

    const int f0 = tid * 2, f1 = tid * 2 + 1;
    const int arow0 = f0 >> 2, akq0 = (f0 & 3) * 4;
    const int arow1 = f1 >> 2, akq1 = (f1 & 3) * 4;
    const int brow0 = f0 >> 5, bcol0 = (f0 & 31) * 4;
    const int brow1 = f1 >> 5, bcol1 = (f1 & 31) * 4;

    float acc[8][8];
    #pragma unroll
    for (int i = 0; i < 8; ++i)
        #pragma unroll
        for (int j = 0; j < 8; ++j) acc[i][j] = 0.f;

    float4 ra0, ra1, rb0, rb1;

    ra0 = *reinterpret_cast<const float4*>(&A[(size_t)(m0 + arow0) * K + akq0]);
    ra1 = *reinterpret_cast<const float4*>(&A[(size_t)(m0 + arow1) * K + akq1]);
    rb0 = *reinterpret_cast<const float4*>(&Bw[(size_t)brow0 * N + n0 + bcol0]);
    rb1 = *reinterpret_cast<const float4*>(&Bw[(size_t)brow1 * N + n0 + bcol1]);
    As[0][akq0 + 0][arow0] = ra0.x; As[0][akq0 + 1][arow0] = ra0.y;
    As[0][akq0 + 2][arow0] = ra0.z; As[0][akq0 + 3][arow0] = ra0.w;
    As[0][akq1 + 0][arow1] = ra1.x; As[0][akq1 + 1][arow1] = ra1.y;
    As[0][akq1 + 2][arow1] = ra1.z; As[0][akq1 + 3][arow1] = ra1.w;
    *reinterpret_cast<float4*>(&Bs[0][brow0][bcol0]) = rb0;
    *reinterpret_cast<float4*>(&Bs[0][brow1][bcol1]) = rb1;
    __syncthreads();

    const int NC = K >> 4;
    for (int c = 0; c < NC; ++c) {
        const int buf = c & 1;
        if (c + 1 < NC) {
            const int kc = (c + 1) << 4;
            ra0 = *reinterpret_cast<const float4*>(&A[(size_t)(m0 + arow0) * K + kc + akq0]);
            ra1 = *reinterpret_cast<const float4*>(&A[(size_t)(m0 + arow1) * K + kc + akq1]);
            rb0 = *reinterpret_cast<const float4*>(&Bw[(size_t)(kc + brow0) * N + n0 + bcol0]);
            rb1 = *reinterpret_cast<const float4*>(&Bw[(size_t)(kc + brow1) * N + n0 + bcol1]);
        }

        #pragma unroll
        for (int k = 0; k < 16; ++k) {
            float4 av0 = *reinterpret_cast<const float4*>(&As[buf][k][tr * 8]);
            float4 av1 = *reinterpret_cast<const float4*>(&As[buf][k][tr * 8 + 4]);
            float4 bv0 = *reinterpret_cast<const float4*>(&Bs[buf][k][tc * 4]);
            float4 bv1 = *reinterpret_cast<const float4*>(&Bs[buf][k][64 + tc * 4]);
            float a[8], b[8];
            a[0]=av0.x; a[1]=av0.y; a[2]=av0.z; a[3]=av0.w;
            a[4]=av1.x; a[5]=av1.y; a[6]=av1.z; a[7]=av1.w;
            b[0]=bv0.x; b[1]=bv0.y; b[2]=bv0.z; b[3]=bv0.w;
            b[4]=bv1.x; b[5]=bv1.y; b[6]=bv1.z; b[7]=bv1.w;
            #pragma unroll
            for (int i = 0; i < 8; ++i)
                #pragma unroll
                for (int j = 0; j < 8; ++j)
                    acc[i][j] += a[i] * b[j];
        }

        if (c + 1 < NC) {
            const int nb = (c + 1) & 1;
            As[nb][akq0 + 0][arow0] = ra0.x; As[nb][akq0 + 1][arow0] = ra0.y;
            As[nb][akq0 + 2][arow0] = ra0.z; As[nb][akq0 + 3][arow0] = ra0.w;
            As[nb][akq1 + 0][arow1] = ra1.x; As[nb][akq1 + 1][arow1] = ra1.y;
            As[nb][akq1 + 2][arow1] = ra1.z; As[nb][akq1 + 3][arow1] = ra1.w;
            *reinterpret_cast<float4*>(&Bs[nb][brow0][bcol0]) = rb0;
            *reinterpret_cast<float4*>(&Bs[nb][brow1][bcol1]) = rb1;
        }
        __syncthreads();
    }

    #pragma unroll
    for (int i = 0; i < 8; ++i) {
        const int m = m0 + tr * 8 + i;
        float4 lo, hi;
        lo.x = acc[i][0] + bias[n0 + tc * 4 + 0];
        lo.y = acc[i][1] + bias[n0 + tc * 4 + 1];
        lo.z = acc[i][2] + bias[n0 + tc * 4 + 2];
        lo.w = acc[i][3] + bias[n0 + tc * 4 + 3];
        hi.x = acc[i][4] + bias[n0 + 64 + tc * 4 + 0];
        hi.y = acc[i][5] + bias[n0 + 64 + tc * 4 + 1];
        hi.z = acc[i][6] + bias[n0 + 64 + tc * 4 + 2];
        hi.w = acc[i][7] + bias[n0 + 64 + tc * 4 + 3];
        *reinterpret_cast<float4*>(&Cc[(size_t)m * N + n0 + tc * 4]) = lo;
        *reinterpret_cast<float4*>(&Cc[(size_t)m * N + n0 + 64 + tc * 4]) = hi;
    }
}

__global__ void __launch_bounds__(256)
qkv_gemm_kernel(const float* __restrict__ x, const float* __restrict__ W,
                const float* __restrict__ bias)
{
    sgemm_core(x, W, bias, g_qkv, MTOT, 3 * Cx, Cx);
}

__global__ void __launch_bounds__(256)
out_gemm_kernel(const float* __restrict__ W, const float* __restrict__ bias,
                float* __restrict__ out)
{
    sgemm_core(g_attn, W, bias, out, MTOT, Cx, Cx);
}

// ---------------------------------------------------------------------------
// RMS norm + RoPE (in place on q,k). One warp per (token, head). [unchanged]
// ---------------------------------------------------------------------------
__global__ void norm_rope_kernel(const float* __restrict__ cosv,
                                 const float* __restrict__ sinv,
                                 const float* __restrict__ gq,
                                 const float* __restrict__ gk)
{
    const int warp = (blockIdx.x * blockDim.x + threadIdx.x) >> 5;
    const int lane = threadIdx.x & 31;
    const int m = warp >> 4;
    const int h = warp & 15;

    const float c = cosv[m * 32 + lane];
    const float s = sinv[m * 32 + lane];

    #pragma unroll
    for (int part = 0; part < 2; ++part) {
        float* ptr = &g_qkv[(size_t)m * 3072 + part * 1024 + h * 64];
        const float* gamma = (part == 0) ? gq : gk;
        float2 v = *reinterpret_cast<float2*>(ptr + 2 * lane);
        float ss = v.x * v.x + v.y * v.y;
        #pragma unroll
        for (int o = 16; o; o >>= 1) ss += __shfl_xor_sync(0xffffffffu, ss, o);
        const float inv = 8.0f / fmaxf(sqrtf(ss), 1e-12f);
        const float re = v.x * inv * gamma[h * 64 + 2 * lane];
        const float im = v.y * inv * gamma[h * 64 + 2 * lane + 1];
        float2 o2;
        o2.x = re * c - im * s;
        o2.y = re * s + im * c;
        *reinterpret_cast<float2*>(ptr + 2 * lane) = o2;
    }
}

// ===========================================================================
// Fused flash attention v4: 64-row q-tiles for 2 blocks/SM (16 warps).
// Same per-thread FMA:LDS ratio as v3 (4-row slices of 8 kept per i-index
// pair), fixed-shift softmax, per-thread partial sums.
// 256 threads: tr = tid>>4 -> rows tr*4..+3; tc = tid&15 -> cols tc*4..+3.
// smem: Qs[64][68] | Ks[64][70] | Vs[64][68] | Ps[64][68] = 68.5 KB
// ===========================================================================
#define FL_QS (64 * 68)
#define FL_KS (64 * 70)
#define FL_VS (64 * 68)
#define FL_PS (64 * 68)
#define FL_SMEM_BYTES ((FL_QS + FL_KS + FL_VS + FL_PS) * 4)

__global__ void __launch_bounds__(256, 2)
flash_attn_kernel()
{
    extern __shared__ float fsm[];
    float* Qs = fsm;
    float* Ks = fsm + FL_QS;
    float* Vs = Ks + FL_KS;
    float* Ps = Vs + FL_VS;

    const int bh = blockIdx.y;
    const int b = bh >> 4, h = bh & 15;
    const int l0 = blockIdx.x * 64;
    const int tid = threadIdx.x;
    const int tr = tid >> 4;     // 0..15 -> q-rows tr*4..+3
    const int tc = tid & 15;     // 0..15 -> key/O cols tc*4..+3

    // Load Q tile (64 rows x 64 d), 1/sqrt(D) folded
    #pragma unroll
    for (int i = 0; i < 4; ++i) {
        const int e = tid + i * 256;
        const int row = e >> 4, c4 = (e & 15) * 4;
        float4 q = *reinterpret_cast<const float4*>(
            &g_qkv[(size_t)(b * Lx + l0 + row) * 3072 + h * 64 + c4]);
        q.x *= 0.125f; q.y *= 0.125f; q.z *= 0.125f; q.w *= 0.125f;
        *reinterpret_cast<float4*>(&Qs[row * 68 + c4]) = q;
    }

    float o[4][4];
    float lrow[4];
    #pragma unroll
    for (int i = 0; i < 4; ++i) {
        lrow[i] = 0.f;
        #pragma unroll
        for (int j = 0; j < 4; ++j) o[i][j] = 0.f;
    }

    for (int kb = 0; kb < Lx / 64; ++kb) {
        __syncthreads();
        // Load K,V tiles (64 keys x 64 d)
        #pragma unroll
        for (int i = 0; i < 4; ++i) {
            const int e = tid + i * 256;
            const int row = e >> 4, c4 = (e & 15) * 4;
            const float* base = &g_qkv[(size_t)(b * Lx + kb * 64 + row) * 3072 + h * 64 + c4];
            float4 kv = *reinterpret_cast<const float4*>(base + 1024);
            float2 k0; k0.x = kv.x; k0.y = kv.y;
            float2 k1; k1.x = kv.z; k1.y = kv.w;
            *reinterpret_cast<float2*>(&Ks[row * 70 + c4]) = k0;
            *reinterpret_cast<float2*>(&Ks[row * 70 + c4 + 2]) = k1;
            float4 vv = *reinterpret_cast<const float4*>(base + 2048);
            *reinterpret_cast<float4*>(&Vs[row * 68 + c4]) = vv;
        }
        __syncthreads();

        // S = Q.K^T (4x4 per thread)
        float s[4][4];
        #pragma unroll
        for (int i = 0; i < 4; ++i)
            #pragma unroll
            for (int j = 0; j < 4; ++j) s[i][j] = 0.f;

        #pragma unroll
        for (int d = 0; d < 64; d += 4) {
            float a[4][4];
            #pragma unroll
            for (int i = 0; i < 4; ++i) {
                float4 av = *reinterpret_cast<const float4*>(&Qs[(tr * 4 + i) * 68 + d]);
                a[i][0] = av.x; a[i][1] = av.y; a[i][2] = av.z; a[i][3] = av.w;
            }
            #pragma unroll
            for (int j = 0; j < 4; ++j) {
                float2 b0 = *reinterpret_cast<const float2*>(&Ks[(tc * 4 + j) * 70 + d]);
                float2 b1 = *reinterpret_cast<const float2*>(&Ks[(tc * 4 + j) * 70 + d + 2]);
                #pragma unroll
                for (int i = 0; i < 4; ++i)
                    s[i][j] += a[i][0] * b0.x + a[i][1] * b0.y
                             + a[i][2] * b1.x + a[i][3] * b1.y;
            }
        }

        // Fixed-shift exp (scores <= 8 provably)
        #pragma unroll
        for (int i = 0; i < 4; ++i) {
            const float p0 = __expf(s[i][0] - 8.0f);
            const float p1 = __expf(s[i][1] - 8.0f);
            const float p2 = __expf(s[i][2] - 8.0f);
            const float p3 = __expf(s[i][3] - 8.0f);
            lrow[i] += (p0 + p1) + (p2 + p3);
            float4 pv; pv.x = p0; pv.y = p1; pv.z = p2; pv.w = p3;
            *reinterpret_cast<float4*>(&Ps[(tr * 4 + i) * 68 + tc * 4]) = pv;
        }
        __syncthreads();

        // O += P.V (4x4 per thread over 64 keys)
        #pragma unroll
        for (int k = 0; k < 64; k += 4) {
            float a[4][4];
            #pragma unroll
            for (int i = 0; i < 4; ++i) {
                float4 av = *reinterpret_cast<const float4*>(&Ps[(tr * 4 + i) * 68 + k]);
                a[i][0] = av.x; a[i][1] = av.y; a[i][2] = av.z; a[i][3] = av.w;
            }
            #pragma unroll
            for (int kk = 0; kk < 4; ++kk) {
                float4 bv = *reinterpret_cast<const float4*>(&Vs[(k + kk) * 68 + tc * 4]);
                #pragma unroll
                for (int i = 0; i < 4; ++i) {
                    o[i][0] += a[i][kk] * bv.x;
                    o[i][1] += a[i][kk] * bv.y;
                    o[i][2] += a[i][kk] * bv.z;
                    o[i][3] += a[i][kk] * bv.w;
                }
            }
        }
    }

    // Reduce row sums across the 16-thread row group, normalize, store.
    #pragma unroll
    for (int i = 0; i < 4; ++i) {
        float l = lrow[i];
        l += __shfl_xor_sync(0xffffffffu, l, 8, 16);
        l += __shfl_xor_sync(0xffffffffu, l, 4, 16);
        l += __shfl_xor_sync(0xffffffffu, l, 2, 16);
        l += __shfl_xor_sync(0xffffffffu, l, 1, 16);
        const float inv = 1.0f / l;
        float4 ov;
        ov.x = o[i][0] * inv; ov.y = o[i][1] * inv;
        ov.z = o[i][2] * inv; ov.w = o[i][3] * inv;
        *reinterpret_cast<float4*>(
            &g_attn[(size_t)(b * Lx + l0 + tr * 4 + i) * 1024 + h * 64 + tc * 4]) = ov;
    }
}

// ---------------------------------------------------------------------------
extern "C" void kernel_launch(void* const* d_in, const int* in_sizes, int n_in,
                              void* d_out, int out_size)
{
    const float* x    = (const float*)d_in[0];
    const float* pcos = (const float*)d_in[1];
    const float* psin = (const float*)d_in[2];
    const float* Wqkv = (const float*)d_in[3];
    const float* bqkv = (const float*)d_in[4];
    const float* gq   = (const float*)d_in[5];
    const float* gk   = (const float*)d_in[6];
    const float* Wout = (const float*)d_in[7];
    const float* bout = (const float*)d_in[8];
    float* out = (float*)d_out;

    cudaFuncSetAttribute(flash_attn_kernel,
                         cudaFuncAttributeMaxDynamicSharedMemorySize, FL_SMEM_BYTES);

    // 1. QKV GEMM + bias -> g_qkv  (128x128 tiles, round-12 core)
    qkv_gemm_kernel<<<dim3(3 * Cx / 128, MTOT / 128), 256>>>(x, Wqkv, bqkv);
    // 2. RMS norm + RoPE in place on q,k
    norm_rope_kernel<<<(MTOT * Hx) / 8, 256>>>(pcos, psin, gq, gk);
    // 3. Fused flash attention (64-row q-tiles, 2 blocks/SM) -> g_attn
    flash_attn_kernel<<<dim3(Lx / 64, Bx * Hx), 256, FL_SMEM_BYTES>>>();
    // 4. Out GEMM + bias -> d_out
    out_gemm_kernel<<<dim3(Cx / 128, MTOT / 128), 256>>>(Wout, bout, out);
}

// round 15
// speedup vs baseline: 1.0057x; 1.0057x over previous
#include <cuda_runtime.h>
#include <math.h>

#define Bx 2
#define Lx 2048
#define Cx 1024
#define Hx 16
#define Dx 64
#define MTOT (Bx*Lx)          // 4096

__device__ float g_qkv[MTOT * 3 * Cx];                      // 50 MB
__device__ float g_attn[MTOT * Cx];                         // 16 MB

// ===========================================================================
// SGEMM 128x128, k-chunks of 16, register-staged double buffer, 1 sync/chunk.
// [round-12 measured best: out 228 us] — verbatim.
// ===========================================================================
__device__ __forceinline__ void sgemm_core(const float* __restrict__ A,
                                           const float* __restrict__ Bw,
                                           const float* __restrict__ bias,
                                           float* __restrict__ Cc,
                                           int M, int N, int K)
{
    __shared__ float As[2][16][128];
    __shared__ float Bs[2][16][128];

    const int tid = threadIdx.x;
    const int m0 = blockIdx.y * 128;
    const int n0 = blockIdx.x * 128;
    const int tr = tid >> 4;
    const int tc = tid & 15;

    const int f0 = tid * 2, f1 = tid * 2 + 1;
    const int arow0 = f0 >> 2, akq0 = (f0 & 3) * 4;
    const int arow1 = f1 >> 2, akq1 = (f1 & 3) * 4;
    const int brow0 = f0 >> 5, bcol0 = (f0 & 31) * 4;
    const int brow1 = f1 >> 5, bcol1 = (f1 & 31) * 4;

    float acc[8][8];
    #pragma unroll
    for (int i = 0; i < 8; ++i)
        #pragma unroll
        for (int j = 0; j < 8; ++j) acc[i][j] = 0.f;

    float4 ra0, ra1, rb0, rb1;

    ra0 = *reinterpret_cast<const float4*>(&A[(size_t)(m0 + arow0) * K + akq0]);
    ra1 = *reinterpret_cast<const float4*>(&A[(size_t)(m0 + arow1) * K + akq1]);
    rb0 = *reinterpret_cast<const float4*>(&Bw[(size_t)brow0 * N + n0 + bcol0]);
    rb1 = *reinterpret_cast<const float4*>(&Bw[(size_t)brow1 * N + n0 + bcol1]);
    As[0][akq0 + 0][arow0] = ra0.x; As[0][akq0 + 1][arow0] = ra0.y;
    As[0][akq0 + 2][arow0] = ra0.z; As[0][akq0 + 3][arow0] = ra0.w;
    As[0][akq1 + 0][arow1] = ra1.x; As[0][akq1 + 1][arow1] = ra1.y;
    As[0][akq1 + 2][arow1] = ra1.z; As[0][akq1 + 3][arow1] = ra1.w;
    *reinterpret_cast<float4*>(&Bs[0][brow0][bcol0]) = rb0;
    *reinterpret_cast<float4*>(&Bs[0][brow1][bcol1]) = rb1;
    __syncthreads();

    const int NC = K >> 4;
    for (int c = 0; c < NC; ++c) {
        const int buf = c & 1;
        if (c + 1 < NC) {
            const int kc = (c + 1) << 4;
            ra0 = *reinterpret_cast<const float4*>(&A[(size_t)(m0 + arow0) * K + kc + akq0]);
            ra1 = *reinterpret_cast<const float4*>(&A[(size_t)(m0 + arow1) * K + kc + akq1]);
            rb0 = *reinterpret_cast<const float4*>(&Bw[(size_t)(kc + brow0) * N + n0 + bcol0]);
            rb1 = *reinterpret_cast<const float4*>(&Bw[(size_t)(kc + brow1) * N + n0 + bcol1]);
        }

        #pragma unroll
        for (int k = 0; k < 16; ++k) {
            float4 av0 = *reinterpret_cast<const float4*>(&As[buf][k][tr * 8]);
            float4 av1 = *reinterpret_cast<const float4*>(&As[buf][k][tr * 8 + 4]);
            float4 bv0 = *reinterpret_cast<const float4*>(&Bs[buf][k][tc * 4]);
            float4 bv1 = *reinterpret_cast<const float4*>(&Bs[buf][k][64 + tc * 4]);
            float a[8], b[8];
            a[0]=av0.x; a[1]=av0.y; a[2]=av0.z; a[3]=av0.w;
            a[4]=av1.x; a[5]=av1.y; a[6]=av1.z; a[7]=av1.w;
            b[0]=bv0.x; b[1]=bv0.y; b[2]=bv0.z; b[3]=bv0.w;
            b[4]=bv1.x; b[5]=bv1.y; b[6]=bv1.z; b[7]=bv1.w;
            #pragma unroll
            for (int i = 0; i < 8; ++i)
                #pragma unroll
                for (int j = 0; j < 8; ++j)
                    acc[i][j] += a[i] * b[j];
        }

        if (c + 1 < NC) {
            const int nb = (c + 1) & 1;
            As[nb][akq0 + 0][arow0] = ra0.x; As[nb][akq0 + 1][arow0] = ra0.y;
            As[nb][akq0 + 2][arow0] = ra0.z; As[nb][akq0 + 3][arow0] = ra0.w;
            As[nb][akq1 + 0][arow1] = ra1.x; As[nb][akq1 + 1][arow1] = ra1.y;
            As[nb][akq1 + 2][arow1] = ra1.z; As[nb][akq1 + 3][arow1] = ra1.w;
            *reinterpret_cast<float4*>(&Bs[nb][brow0][bcol0]) = rb0;
            *reinterpret_cast<float4*>(&Bs[nb][brow1][bcol1]) = rb1;
        }
        __syncthreads();
    }

    #pragma unroll
    for (int i = 0; i < 8; ++i) {
        const int m = m0 + tr * 8 + i;
        float4 lo, hi;
        lo.x = acc[i][0] + bias[n0 + tc * 4 + 0];
        lo.y = acc[i][1] + bias[n0 + tc * 4 + 1];
        lo.z = acc[i][2] + bias[n0 + tc * 4 + 2];
        lo.w = acc[i][3] + bias[n0 + tc * 4 + 3];
        hi.x = acc[i][4] + bias[n0 + 64 + tc * 4 + 0];
        hi.y = acc[i][5] + bias[n0 + 64 + tc * 4 + 1];
        hi.z = acc[i][6] + bias[n0 + 64 + tc * 4 + 2];
        hi.w = acc[i][7] + bias[n0 + 64 + tc * 4 + 3];
        *reinterpret_cast<float4*>(&Cc[(size_t)m * N + n0 + tc * 4]) = lo;
        *reinterpret_cast<float4*>(&Cc[(size_t)m * N + n0 + 64 + tc * 4]) = hi;
    }
}

__global__ void __launch_bounds__(256)
qkv_gemm_kernel(const float* __restrict__ x, const float* __restrict__ W,
                const float* __restrict__ bias)
{
    sgemm_core(x, W, bias, g_qkv, MTOT, 3 * Cx, Cx);
}

__global__ void __launch_bounds__(256)
out_gemm_kernel(const float* __restrict__ W, const float* __restrict__ bias,
                float* __restrict__ out)
{
    sgemm_core(g_attn, W, bias, out, MTOT, Cx, Cx);
}

// ---------------------------------------------------------------------------
// RMS norm + RoPE (in place on q,k). One warp per (token, head). [unchanged]
// ---------------------------------------------------------------------------
__global__ void norm_rope_kernel(const float* __restrict__ cosv,
                                 const float* __restrict__ sinv,
                                 const float* __restrict__ gq,
                                 const float* __restrict__ gk)
{
    const int warp = (blockIdx.x * blockDim.x + threadIdx.x) >> 5;
    const int lane = threadIdx.x & 31;
    const int m = warp >> 4;
    const int h = warp & 15;

    const float c = cosv[m * 32 + lane];
    const float s = sinv[m * 32 + lane];

    #pragma unroll
    for (int part = 0; part < 2; ++part) {
        float* ptr = &g_qkv[(size_t)m * 3072 + part * 1024 + h * 64];
        const float* gamma = (part == 0) ? gq : gk;
        float2 v = *reinterpret_cast<float2*>(ptr + 2 * lane);
        float ss = v.x * v.x + v.y * v.y;
        #pragma unroll
        for (int o = 16; o; o >>= 1) ss += __shfl_xor_sync(0xffffffffu, ss, o);
        const float inv = 8.0f / fmaxf(sqrtf(ss), 1e-12f);
        const float re = v.x * inv * gamma[h * 64 + 2 * lane];
        const float im = v.y * inv * gamma[h * 64 + 2 * lane + 1];
        float2 o2;
        o2.x = re * c - im * s;
        o2.y = re * s + im * c;
        *reinterpret_cast<float2*>(ptr + 2 * lane) = o2;
    }
}

// ===========================================================================
// Fused flash attention v3 [round-12 structure, byte-identical] with
// __launch_bounds__(256, 2): regs capped at 128 so 2 blocks/SM co-reside
// (2 x 102.5 KB smem = 205 KB <= 228 KB/SM), doubling warps at UNCHANGED
// per-thread arithmetic intensity (the round-13/14 lesson).
// ===========================================================================
#define FL_QS (128 * 68)
#define FL_KS (64 * 70)
#define FL_VS (64 * 68)
#define FL_PS (128 * 68)
#define FL_SMEM_BYTES ((FL_QS + FL_KS + FL_VS + FL_PS) * 4)

__global__ void __launch_bounds__(256, 2)
flash_attn_kernel()
{
    extern __shared__ float fsm[];
    float* Qs = fsm;
    float* Ks = fsm + FL_QS;
    float* Vs = Ks + FL_KS;
    float* Ps = Vs + FL_VS;

    const int bh = blockIdx.y;
    const int b = bh >> 4, h = bh & 15;
    const int l0 = blockIdx.x * 128;
    const int tid = threadIdx.x;
    const int tr = tid >> 4;
    const int tc = tid & 15;

    #pragma unroll
    for (int i = 0; i < 8; ++i) {
        const int e = tid + i * 256;
        const int row = e >> 4, c4 = (e & 15) * 4;
        float4 q = *reinterpret_cast<const float4*>(
            &g_qkv[(size_t)(b * Lx + l0 + row) * 3072 + h * 64 + c4]);
        q.x *= 0.125f; q.y *= 0.125f; q.z *= 0.125f; q.w *= 0.125f;
        *reinterpret_cast<float4*>(&Qs[row * 68 + c4]) = q;
    }

    float o[8][4];
    float lrow[8];
    #pragma unroll
    for (int i = 0; i < 8; ++i) {
        lrow[i] = 0.f;
        #pragma unroll
        for (int j = 0; j < 4; ++j) o[i][j] = 0.f;
    }

    for (int kb = 0; kb < Lx / 64; ++kb) {
        __syncthreads();
        #pragma unroll
        for (int i = 0; i < 4; ++i) {
            const int e = tid + i * 256;
            const int row = e >> 4, c4 = (e & 15) * 4;
            const float* base = &g_qkv[(size_t)(b * Lx + kb * 64 + row) * 3072 + h * 64 + c4];
            float4 kv = *reinterpret_cast<const float4*>(base + 1024);
            float2 k0; k0.x = kv.x; k0.y = kv.y;
            float2 k1; k1.x = kv.z; k1.y = kv.w;
            *reinterpret_cast<float2*>(&Ks[row * 70 + c4]) = k0;
            *reinterpret_cast<float2*>(&Ks[row * 70 + c4 + 2]) = k1;
            float4 vv = *reinterpret_cast<const float4*>(base + 2048);
            *reinterpret_cast<float4*>(&Vs[row * 68 + c4]) = vv;
        }
        __syncthreads();

        float s[8][4];
        #pragma unroll
        for (int i = 0; i < 8; ++i)
            #pragma unroll
            for (int j = 0; j < 4; ++j) s[i][j] = 0.f;

        #pragma unroll
        for (int d = 0; d < 64; d += 4) {
            float a[8][4];
            #pragma unroll
            for (int i = 0; i < 8; ++i) {
                float4 av = *reinterpret_cast<const float4*>(&Qs[(tr * 8 + i) * 68 + d]);
                a[i][0] = av.x; a[i][1] = av.y; a[i][2] = av.z; a[i][3] = av.w;
            }
            #pragma unroll
            for (int j = 0; j < 4; ++j) {
                float2 b0 = *reinterpret_cast<const float2*>(&Ks[(tc * 4 + j) * 70 + d]);
                float2 b1 = *reinterpret_cast<const float2*>(&Ks[(tc * 4 + j) * 70 + d + 2]);
                #pragma unroll
                for (int i = 0; i < 8; ++i)
                    s[i][j] += a[i][0] * b0.x + a[i][1] * b0.y
                             + a[i][2] * b1.x + a[i][3] * b1.y;
            }
        }

        #pragma unroll
        for (int i = 0; i < 8; ++i) {
            const float p0 = __expf(s[i][0] - 8.0f);
            const float p1 = __expf(s[i][1] - 8.0f);
            const float p2 = __expf(s[i][2] - 8.0f);
            const float p3 = __expf(s[i][3] - 8.0f);
            lrow[i] += (p0 + p1) + (p2 + p3);
            float4 pv; pv.x = p0; pv.y = p1; pv.z = p2; pv.w = p3;
            *reinterpret_cast<float4*>(&Ps[(tr * 8 + i) * 68 + tc * 4]) = pv;
        }
        __syncthreads();

        #pragma unroll
        for (int k = 0; k < 64; k += 4) {
            float a[8][4];
            #pragma unroll
            for (int i = 0; i < 8; ++i) {
                float4 av = *reinterpret_cast<const float4*>(&Ps[(tr * 8 + i) * 68 + k]);
                a[i][0] = av.x; a[i][1] = av.y; a[i][2] = av.z; a[i][3] = av.w;
            }
            #pragma unroll
            for (int kk = 0; kk < 4; ++kk) {
                float4 bv = *reinterpret_cast<const float4*>(&Vs[(k + kk) * 68 + tc * 4]);
                #pragma unroll
                for (int i = 0; i < 8; ++i) {
                    o[i][0] += a[i][kk] * bv.x;
                    o[i][1] += a[i][kk] * bv.y;
                    o[i][2] += a[i][kk] * bv.z;
                    o[i][3] += a[i][kk] * bv.w;
                }
            }
        }
    }

    #pragma unroll
    for (int i = 0; i < 8; ++i) {
        float l = lrow[i];
        l += __shfl_xor_sync(0xffffffffu, l, 8, 16);
        l += __shfl_xor_sync(0xffffffffu, l, 4, 16);
        l += __shfl_xor_sync(0xffffffffu, l, 2, 16);
        l += __shfl_xor_sync(0xffffffffu, l, 1, 16);
        const float inv = 1.0f / l;
        float4 ov;
        ov.x = o[i][0] * inv; ov.y = o[i][1] * inv;
        ov.z = o[i][2] * inv; ov.w = o[i][3] * inv;
        *reinterpret_cast<float4*>(
            &g_attn[(size_t)(b * Lx + l0 + tr * 8 + i) * 1024 + h * 64 + tc * 4]) = ov;
    }
}

// ---------------------------------------------------------------------------
extern "C" void kernel_launch(void* const* d_in, const int* in_sizes, int n_in,
                              void* d_out, int out_size)
{
    const float* x    = (const float*)d_in[0];
    const float* pcos = (const float*)d_in[1];
    const float* psin = (const float*)d_in[2];
    const float* Wqkv = (const float*)d_in[3];
    const float* bqkv = (const float*)d_in[4];
    const float* gq   = (const float*)d_in[5];
    const float* gk   = (const float*)d_in[6];
    const float* Wout = (const float*)d_in[7];
    const float* bout = (const float*)d_in[8];
    float* out = (float*)d_out;

    cudaFuncSetAttribute(flash_attn_kernel,
                         cudaFuncAttributeMaxDynamicSharedMemorySize, FL_SMEM_BYTES);

    // 1. QKV GEMM + bias -> g_qkv
    qkv_gemm_kernel<<<dim3(3 * Cx / 128, MTOT / 128), 256>>>(x, Wqkv, bqkv);
    // 2. RMS norm + RoPE in place on q,k
    norm_rope_kernel<<<(MTOT * Hx) / 8, 256>>>(pcos, psin, gq, gk);
    // 3. Fused flash attention (2 blocks/SM) -> g_attn
    flash_attn_kernel<<<dim3(Lx / 128, Bx * Hx), 256, FL_SMEM_BYTES>>>();
    // 4. Out GEMM + bias -> d_out
    out_gemm_kernel<<<dim3(Cx / 128, MTOT / 128), 256>>>(Wout, bout, out);
}

// round 16
// speedup vs baseline: 1.0375x; 1.0317x over previous
#include <cuda_runtime.h>
#include <math.h>

#define Bx 2
#define Lx 2048
#define Cx 1024
#define Hx 16
#define Dx 64
#define MTOT (Bx*Lx)          // 4096

__device__ float g_qkv[MTOT * 3 * Cx];                      // 50 MB
__device__ float g_attn[MTOT * Cx];                         // 16 MB

// ===========================================================================
// SGEMM 128x128, k-chunks of 16, register-staged double buffer, 1 sync/chunk.
// [round-12 measured best] — verbatim.
// ===========================================================================
__device__ __forceinline__ void sgemm_core(const float* __restrict__ A,
                                           const float* __restrict__ Bw,
                                           const float* __restrict__ bias,
                                           float* __restrict__ Cc,
                                           int M, int N, int K)
{
    __shared__ float As[2][16][128];
    __shared__ float Bs[2][16][128];

    const int tid = threadIdx.x;
    const int m0 = blockIdx.y * 128;
    const int n0 = blockIdx.x * 128;
    const int tr = tid >> 4;
    const int tc = tid & 15;

    const int f0 = tid * 2, f1 = tid * 2 + 1;
    const int arow0 = f0 >> 2, akq0 = (f0 & 3) * 4;
    const int arow1 = f1 >> 2, akq1 = (f1 & 3) * 4;
    const int brow0 = f0 >> 5, bcol0 = (f0 & 31) * 4;
    const int brow1 = f1 >> 5, bcol1 = (f1 & 31) * 4;

    float acc[8][8];
    #pragma unroll
    for (int i = 0; i < 8; ++i)
        #pragma unroll
        for (int j = 0; j < 8; ++j) acc[i][j] = 0.f;

    float4 ra0, ra1, rb0, rb1;

    ra0 = *reinterpret_cast<const float4*>(&A[(size_t)(m0 + arow0) * K + akq0]);
    ra1 = *reinterpret_cast<const float4*>(&A[(size_t)(m0 + arow1) * K + akq1]);
    rb0 = *reinterpret_cast<const float4*>(&Bw[(size_t)brow0 * N + n0 + bcol0]);
    rb1 = *reinterpret_cast<const float4*>(&Bw[(size_t)brow1 * N + n0 + bcol1]);
    As[0][akq0 + 0][arow0] = ra0.x; As[0][akq0 + 1][arow0] = ra0.y;
    As[0][akq0 + 2][arow0] = ra0.z; As[0][akq0 + 3][arow0] = ra0.w;
    As[0][akq1 + 0][arow1] = ra1.x; As[0][akq1 + 1][arow1] = ra1.y;
    As[0][akq1 + 2][arow1] = ra1.z; As[0][akq1 + 3][arow1] = ra1.w;
    *reinterpret_cast<float4*>(&Bs[0][brow0][bcol0]) = rb0;
    *reinterpret_cast<float4*>(&Bs[0][brow1][bcol1]) = rb1;
    __syncthreads();

    const int NC = K >> 4;
    for (int c = 0; c < NC; ++c) {
        const int buf = c & 1;
        if (c + 1 < NC) {
            const int kc = (c + 1) << 4;
            ra0 = *reinterpret_cast<const float4*>(&A[(size_t)(m0 + arow0) * K + kc + akq0]);
            ra1 = *reinterpret_cast<const float4*>(&A[(size_t)(m0 + arow1) * K + kc + akq1]);
            rb0 = *reinterpret_cast<const float4*>(&Bw[(size_t)(kc + brow0) * N + n0 + bcol0]);
            rb1 = *reinterpret_cast<const float4*>(&Bw[(size_t)(kc + brow1) * N + n0 + bcol1]);
        }

        #pragma unroll
        for (int k = 0; k < 16; ++k) {
            float4 av0 = *reinterpret_cast<const float4*>(&As[buf][k][tr * 8]);
            float4 av1 = *reinterpret_cast<const float4*>(&As[buf][k][tr * 8 + 4]);
            float4 bv0 = *reinterpret_cast<const float4*>(&Bs[buf][k][tc * 4]);
            float4 bv1 = *reinterpret_cast<const float4*>(&Bs[buf][k][64 + tc * 4]);
            float a[8], b[8];
            a[0]=av0.x; a[1]=av0.y; a[2]=av0.z; a[3]=av0.w;
            a[4]=av1.x; a[5]=av1.y; a[6]=av1.z; a[7]=av1.w;
            b[0]=bv0.x; b[1]=bv0.y; b[2]=bv0.z; b[3]=bv0.w;
            b[4]=bv1.x; b[5]=bv1.y; b[6]=bv1.z; b[7]=bv1.w;
            #pragma unroll
            for (int i = 0; i < 8; ++i)
                #pragma unroll
                for (int j = 0; j < 8; ++j)
                    acc[i][j] += a[i] * b[j];
        }

        if (c + 1 < NC) {
            const int nb = (c + 1) & 1;
            As[nb][akq0 + 0][arow0] = ra0.x; As[nb][akq0 + 1][arow0] = ra0.y;
            As[nb][akq0 + 2][arow0] = ra0.z; As[nb][akq0 + 3][arow0] = ra0.w;
            As[nb][akq1 + 0][arow1] = ra1.x; As[nb][akq1 + 1][arow1] = ra1.y;
            As[nb][akq1 + 2][arow1] = ra1.z; As[nb][akq1 + 3][arow1] = ra1.w;
            *reinterpret_cast<float4*>(&Bs[nb][brow0][bcol0]) = rb0;
            *reinterpret_cast<float4*>(&Bs[nb][brow1][bcol1]) = rb1;
        }
        __syncthreads();
    }

    #pragma unroll
    for (int i = 0; i < 8; ++i) {
        const int m = m0 + tr * 8 + i;
        float4 lo, hi;
        lo.x = acc[i][0] + bias[n0 + tc * 4 + 0];
        lo.y = acc[i][1] + bias[n0 + tc * 4 + 1];
        lo.z = acc[i][2] + bias[n0 + tc * 4 + 2];
        lo.w = acc[i][3] + bias[n0 + tc * 4 + 3];
        hi.x = acc[i][4] + bias[n0 + 64 + tc * 4 + 0];
        hi.y = acc[i][5] + bias[n0 + 64 + tc * 4 + 1];
        hi.z = acc[i][6] + bias[n0 + 64 + tc * 4 + 2];
        hi.w = acc[i][7] + bias[n0 + 64 + tc * 4 + 3];
        *reinterpret_cast<float4*>(&Cc[(size_t)m * N + n0 + tc * 4]) = lo;
        *reinterpret_cast<float4*>(&Cc[(size_t)m * N + n0 + 64 + tc * 4]) = hi;
    }
}

__global__ void __launch_bounds__(256)
qkv_gemm_kernel(const float* __restrict__ x, const float* __restrict__ W,
                const float* __restrict__ bias)
{
    sgemm_core(x, W, bias, g_qkv, MTOT, 3 * Cx, Cx);
}

__global__ void __launch_bounds__(256)
out_gemm_kernel(const float* __restrict__ W, const float* __restrict__ bias,
                float* __restrict__ out)
{
    sgemm_core(g_attn, W, bias, out, MTOT, Cx, Cx);
}

// ---------------------------------------------------------------------------
// RMS norm + RoPE (in place on q,k). One warp per (token, head). [unchanged]
// ---------------------------------------------------------------------------
__global__ void norm_rope_kernel(const float* __restrict__ cosv,
                                 const float* __restrict__ sinv,
                                 const float* __restrict__ gq,
                                 const float* __restrict__ gk)
{
    const int warp = (blockIdx.x * blockDim.x + threadIdx.x) >> 5;
    const int lane = threadIdx.x & 31;
    const int m = warp >> 4;
    const int h = warp & 15;

    const float c = cosv[m * 32 + lane];
    const float s = sinv[m * 32 + lane];

    #pragma unroll
    for (int part = 0; part < 2; ++part) {
        float* ptr = &g_qkv[(size_t)m * 3072 + part * 1024 + h * 64];
        const float* gamma = (part == 0) ? gq : gk;
        float2 v = *reinterpret_cast<float2*>(ptr + 2 * lane);
        float ss = v.x * v.x + v.y * v.y;
        #pragma unroll
        for (int o = 16; o; o >>= 1) ss += __shfl_xor_sync(0xffffffffu, ss, o);
        const float inv = 8.0f / fmaxf(sqrtf(ss), 1e-12f);
        const float re = v.x * inv * gamma[h * 64 + 2 * lane];
        const float im = v.y * inv * gamma[h * 64 + 2 * lane + 1];
        float2 o2;
        o2.x = re * c - im * s;
        o2.y = re * s + im * c;
        *reinterpret_cast<float2*>(ptr + 2 * lane) = o2;
    }
}

// ===========================================================================
// Fused flash attention v5: round-12 structure + double-buffered K/V smem
// with register prefetch. Next tile's LDGs issue before the QK compute
// (~4096 FMA of latency cover); STS lands in the alternate buffer after the
// mid-tile sync. Sync count per tile unchanged (2). 1 block/SM (137 KB smem),
// 8 warps — the measured-best residency for this kernel.
// ===========================================================================
#define FL_QS (128 * 68)
#define FL_KS (64 * 70)
#define FL_VS (64 * 68)
#define FL_PS (128 * 68)
#define FL_SMEM_BYTES ((FL_QS + 2 * FL_KS + 2 * FL_VS + FL_PS) * 4)

__global__ void __launch_bounds__(256)
flash_attn_kernel()
{
    extern __shared__ float fsm[];
    float* Qs  = fsm;
    float* Ks0 = fsm + FL_QS;
    float* Ks1 = Ks0 + FL_KS;
    float* Vs0 = Ks1 + FL_KS;
    float* Vs1 = Vs0 + FL_VS;
    float* Ps  = Vs1 + FL_VS;

    const int bh = blockIdx.y;
    const int b = bh >> 4, h = bh & 15;
    const int l0 = blockIdx.x * 128;
    const int tid = threadIdx.x;
    const int tr = tid >> 4;
    const int tc = tid & 15;

    // Per-thread loader coords (4 rows of the 64-key tile)
    const int lrw = tid >> 4;            // 0..15, +16 per i
    const int lc4 = (tid & 15) * 4;      // 0..60

    // Load Q tile (scaled by 1/sqrt(D))
    #pragma unroll
    for (int i = 0; i < 8; ++i) {
        const int e = tid + i * 256;
        const int row = e >> 4, c4 = (e & 15) * 4;
        float4 q = *reinterpret_cast<const float4*>(
            &g_qkv[(size_t)(b * Lx + l0 + row) * 3072 + h * 64 + c4]);
        q.x *= 0.125f; q.y *= 0.125f; q.z *= 0.125f; q.w *= 0.125f;
        *reinterpret_cast<float4*>(&Qs[row * 68 + c4]) = q;
    }

    // Prologue: tile 0 -> buffers 0
    float4 rk[4], rv[4];
    #pragma unroll
    for (int i = 0; i < 4; ++i) {
        const int row = lrw + i * 16;
        const float* base = &g_qkv[(size_t)(b * Lx + row) * 3072 + h * 64 + lc4];
        rk[i] = *reinterpret_cast<const float4*>(base + 1024);
        rv[i] = *reinterpret_cast<const float4*>(base + 2048);
    }
    #pragma unroll
    for (int i = 0; i < 4; ++i) {
        const int row = lrw + i * 16;
        *reinterpret_cast<float2*>(&Ks0[row * 70 + lc4]) = make_float2(rk[i].x, rk[i].y);
        *reinterpret_cast<float2*>(&Ks0[row * 70 + lc4 + 2]) = make_float2(rk[i].z, rk[i].w);
        *reinterpret_cast<float4*>(&Vs0[row * 68 + lc4]) = rv[i];
    }
    __syncthreads();

    float o[8][4];
    float lrow[8];
    #pragma unroll
    for (int i = 0; i < 8; ++i) {
        lrow[i] = 0.f;
        #pragma unroll
        for (int j = 0; j < 4; ++j) o[i][j] = 0.f;
    }

    for (int kb = 0; kb < Lx / 64; ++kb) {
        float* Kcur = (kb & 1) ? Ks1 : Ks0;
        float* Vcur = (kb & 1) ? Vs1 : Vs0;
        float* Knxt = (kb & 1) ? Ks0 : Ks1;
        float* Vnxt = (kb & 1) ? Vs0 : Vs1;
        const bool havenext = (kb + 1) < (Lx / 64);

        // Prefetch next tile to registers (overlaps with QK compute below)
        if (havenext) {
            #pragma unroll
            for (int i = 0; i < 4; ++i) {
                const int row = lrw + i * 16;
                const float* base =
                    &g_qkv[(size_t)(b * Lx + (kb + 1) * 64 + row) * 3072 + h * 64 + lc4];
                rk[i] = *reinterpret_cast<const float4*>(base + 1024);
                rv[i] = *reinterpret_cast<const float4*>(base + 2048);
            }
        }

        // S = Q.K^T
        float s[8][4];
        #pragma unroll
        for (int i = 0; i < 8; ++i)
            #pragma unroll
            for (int j = 0; j < 4; ++j) s[i][j] = 0.f;

        #pragma unroll
        for (int d = 0; d < 64; d += 4) {
            float a[8][4];
            #pragma unroll
            for (int i = 0; i < 8; ++i) {
                float4 av = *reinterpret_cast<const float4*>(&Qs[(tr * 8 + i) * 68 + d]);
                a[i][0] = av.x; a[i][1] = av.y; a[i][2] = av.z; a[i][3] = av.w;
            }
            #pragma unroll
            for (int j = 0; j < 4; ++j) {
                float2 b0 = *reinterpret_cast<const float2*>(&Kcur[(tc * 4 + j) * 70 + d]);
                float2 b1 = *reinterpret_cast<const float2*>(&Kcur[(tc * 4 + j) * 70 + d + 2]);
                #pragma unroll
                for (int i = 0; i < 8; ++i)
                    s[i][j] += a[i][0] * b0.x + a[i][1] * b0.y
                             + a[i][2] * b1.x + a[i][3] * b1.y;
            }
        }

        // Fixed-shift exp (scores provably <= 8)
        #pragma unroll
        for (int i = 0; i < 8; ++i) {
            const float p0 = __expf(s[i][0] - 8.0f);
            const float p1 = __expf(s[i][1] - 8.0f);
            const float p2 = __expf(s[i][2] - 8.0f);
            const float p3 = __expf(s[i][3] - 8.0f);
            lrow[i] += (p0 + p1) + (p2 + p3);
            float4 pv; pv.x = p0; pv.y = p1; pv.z = p2; pv.w = p3;
            *reinterpret_cast<float4*>(&Ps[(tr * 8 + i) * 68 + tc * 4]) = pv;
        }
        // Sync: (a) Ps visible for PV, (b) all warps finished PV of tile kb-1,
        // which was the last reader of the buffer STS below writes.
        __syncthreads();

        if (havenext) {
            #pragma unroll
            for (int i = 0; i < 4; ++i) {
                const int row = lrw + i * 16;
                *reinterpret_cast<float2*>(&Knxt[row * 70 + lc4]) = make_float2(rk[i].x, rk[i].y);
                *reinterpret_cast<float2*>(&Knxt[row * 70 + lc4 + 2]) = make_float2(rk[i].z, rk[i].w);
                *reinterpret_cast<float4*>(&Vnxt[row * 68 + lc4]) = rv[i];
            }
        }

        // O += P.V
        #pragma unroll
        for (int k = 0; k < 64; k += 4) {
            float a[8][4];
            #pragma unroll
            for (int i = 0; i < 8; ++i) {
                float4 av = *reinterpret_cast<const float4*>(&Ps[(tr * 8 + i) * 68 + k]);
                a[i][0] = av.x; a[i][1] = av.y; a[i][2] = av.z; a[i][3] = av.w;
            }
            #pragma unroll
            for (int kk = 0; kk < 4; ++kk) {
                float4 bv = *reinterpret_cast<const float4*>(&Vcur[(k + kk) * 68 + tc * 4]);
                #pragma unroll
                for (int i = 0; i < 8; ++i) {
                    o[i][0] += a[i][kk] * bv.x;
                    o[i][1] += a[i][kk] * bv.y;
                    o[i][2] += a[i][kk] * bv.z;
                    o[i][3] += a[i][kk] * bv.w;
                }
            }
        }
        // Sync: next QK reads Knxt (STS above); next exp overwrites Ps.
        __syncthreads();
    }

    #pragma unroll
    for (int i = 0; i < 8; ++i) {
        float l = lrow[i];
        l += __shfl_xor_sync(0xffffffffu, l, 8, 16);
        l += __shfl_xor_sync(0xffffffffu, l, 4, 16);
        l += __shfl_xor_sync(0xffffffffu, l, 2, 16);
        l += __shfl_xor_sync(0xffffffffu, l, 1, 16);
        const float inv = 1.0f / l;
        float4 ov;
        ov.x = o[i][0] * inv; ov.y = o[i][1] * inv;
        ov.z = o[i][2] * inv; ov.w = o[i][3] * inv;
        *reinterpret_cast<float4*>(
            &g_attn[(size_t)(b * Lx + l0 + tr * 8 + i) * 1024 + h * 64 + tc * 4]) = ov;
    }
}

// ---------------------------------------------------------------------------
extern "C" void kernel_launch(void* const* d_in, const int* in_sizes, int n_in,
                              void* d_out, int out_size)
{
    const float* x    = (const float*)d_in[0];
    const float* pcos = (const float*)d_in[1];
    const float* psin = (const float*)d_in[2];
    const float* Wqkv = (const float*)d_in[3];
    const float* bqkv = (const float*)d_in[4];
    const float* gq   = (const float*)d_in[5];
    const float* gk   = (const float*)d_in[6];
    const float* Wout = (const float*)d_in[7];
    const float* bout = (const float*)d_in[8];
    float* out = (float*)d_out;

    cudaFuncSetAttribute(flash_attn_kernel,
                         cudaFuncAttributeMaxDynamicSharedMemorySize, FL_SMEM_BYTES);

    // 1. QKV GEMM + bias -> g_qkv
    qkv_gemm_kernel<<<dim3(3 * Cx / 128, MTOT / 128), 256>>>(x, Wqkv, bqkv);
    // 2. RMS norm + RoPE in place on q,k
    norm_rope_kernel<<<(MTOT * Hx) / 8, 256>>>(pcos, psin, gq, gk);
    // 3. Fused flash attention (double-buffered K/V prefetch) -> g_attn
    flash_attn_kernel<<<dim3(Lx / 128, Bx * Hx), 256, FL_SMEM_BYTES>>>();
    // 4. Out GEMM + bias -> d_out
    out_gemm_kernel<<<dim3(Cx / 128, MTOT / 128), 256>>>(Wout, bout, out);
}

// round 17
// speedup vs baseline: 1.0600x; 1.0217x over previous
#include <cuda_runtime.h>
#include <math.h>

#define Bx 2
#define Lx 2048
#define Cx 1024
#define Hx 16
#define Dx 64
#define MTOT (Bx*Lx)          // 4096

__device__ float g_qkv[MTOT * 3 * Cx];                      // 50 MB
__device__ float g_attn[MTOT * Cx];                         // 16 MB

// ---------------------------------------------------------------------------
// Packed fp32 helpers (f32x2: base sm_100 feature per PTX ISA)
// ---------------------------------------------------------------------------
typedef unsigned long long ull;

__device__ __forceinline__ ull pack2(float lo, float hi) {
    ull r;
    asm("mov.b64 %0, {%1, %2};" : "=l"(r) : "f"(lo), "f"(hi));
    return r;
}
__device__ __forceinline__ void unpack2(ull v, float& lo, float& hi) {
    asm("mov.b64 {%0, %1}, %2;" : "=f"(lo), "=f"(hi) : "l"(v));
}
#define FFMA2(d, a, b) \
    asm("fma.rn.f32x2 %0, %1, %2, %0;" : "+l"(d) : "l"(a), "l"(b))

// ===========================================================================
// SGEMM 128x128, k-chunks of 16, register-staged double buffer, 1 sync/chunk
// [round-12 structure] with packed f32x2 FMA inner loop:
// rows packed in pairs -> 32 named ull accumulators, 32 FFMA2 + 12 mov
// + 4 LDS.128 per k (vs 64 FFMA + 4 LDS scalar).
// ===========================================================================
__device__ __forceinline__ void sgemm_core(const float* __restrict__ A,
                                           const float* __restrict__ Bw,
                                           const float* __restrict__ bias,
                                           float* __restrict__ Cc,
                                           int M, int N, int K)
{
    __shared__ float As[2][16][128];
    __shared__ float Bs[2][16][128];

    const int tid = threadIdx.x;
    const int m0 = blockIdx.y * 128;
    const int n0 = blockIdx.x * 128;
    const int tr = tid >> 4;
    const int tc = tid & 15;

    const int f0 = tid * 2, f1 = tid * 2 + 1;
    const int arow0 = f0 >> 2, akq0 = (f0 & 3) * 4;
    const int arow1 = f1 >> 2, akq1 = (f1 & 3) * 4;
    const int brow0 = f0 >> 5, bcol0 = (f0 & 31) * 4;
    const int brow1 = f1 >> 5, bcol1 = (f1 & 31) * 4;

    // 32 named packed accumulators: cIJ = rows (tr*8+2I, tr*8+2I+1), col J.
    ull c00=0, c01=0, c02=0, c03=0, c04=0, c05=0, c06=0, c07=0;
    ull c10=0, c11=0, c12=0, c13=0, c14=0, c15=0, c16=0, c17=0;
    ull c20=0, c21=0, c22=0, c23=0, c24=0, c25=0, c26=0, c27=0;
    ull c30=0, c31=0, c32=0, c33=0, c34=0, c35=0, c36=0, c37=0;

    float4 ra0, ra1, rb0, rb1;

    ra0 = *reinterpret_cast<const float4*>(&A[(size_t)(m0 + arow0) * K + akq0]);
    ra1 = *reinterpret_cast<const float4*>(&A[(size_t)(m0 + arow1) * K + akq1]);
    rb0 = *reinterpret_cast<const float4*>(&Bw[(size_t)brow0 * N + n0 + bcol0]);
    rb1 = *reinterpret_cast<const float4*>(&Bw[(size_t)brow1 * N + n0 + bcol1]);
    As[0][akq0 + 0][arow0] = ra0.x; As[0][akq0 + 1][arow0] = ra0.y;
    As[0][akq0 + 2][arow0] = ra0.z; As[0][akq0 + 3][arow0] = ra0.w;
    As[0][akq1 + 0][arow1] = ra1.x; As[0][akq1 + 1][arow1] = ra1.y;
    As[0][akq1 + 2][arow1] = ra1.z; As[0][akq1 + 3][arow1] = ra1.w;
    *reinterpret_cast<float4*>(&Bs[0][brow0][bcol0]) = rb0;
    *reinterpret_cast<float4*>(&Bs[0][brow1][bcol1]) = rb1;
    __syncthreads();

    const int NC = K >> 4;
    for (int c = 0; c < NC; ++c) {
        const int buf = c & 1;
        if (c + 1 < NC) {
            const int kc = (c + 1) << 4;
            ra0 = *reinterpret_cast<const float4*>(&A[(size_t)(m0 + arow0) * K + kc + akq0]);
            ra1 = *reinterpret_cast<const float4*>(&A[(size_t)(m0 + arow1) * K + kc + akq1]);
            rb0 = *reinterpret_cast<const float4*>(&Bw[(size_t)(kc + brow0) * N + n0 + bcol0]);
            rb1 = *reinterpret_cast<const float4*>(&Bw[(size_t)(kc + brow1) * N + n0 + bcol1]);
        }

        #pragma unroll
        for (int k = 0; k < 16; ++k) {
            float4 av0 = *reinterpret_cast<const float4*>(&As[buf][k][tr * 8]);
            float4 av1 = *reinterpret_cast<const float4*>(&As[buf][k][tr * 8 + 4]);
            float4 bv0 = *reinterpret_cast<const float4*>(&Bs[buf][k][tc * 4]);
            float4 bv1 = *reinterpret_cast<const float4*>(&Bs[buf][k][64 + tc * 4]);

            const ull a0 = pack2(av0.x, av0.y);   // rows 0,1
            const ull a1 = pack2(av0.z, av0.w);   // rows 2,3
            const ull a2 = pack2(av1.x, av1.y);   // rows 4,5
            const ull a3 = pack2(av1.z, av1.w);   // rows 6,7
            const ull b0 = pack2(bv0.x, bv0.x);
            const ull b1 = pack2(bv0.y, bv0.y);
            const ull b2 = pack2(bv0.z, bv0.z);
            const ull b3 = pack2(bv0.w, bv0.w);
            const ull b4 = pack2(bv1.x, bv1.x);
            const ull b5 = pack2(bv1.y, bv1.y);
            const ull b6 = pack2(bv1.z, bv1.z);
            const ull b7 = pack2(bv1.w, bv1.w);

            FFMA2(c00, a0, b0); FFMA2(c01, a0, b1);
            FFMA2(c02, a0, b2); FFMA2(c03, a0, b3);
            FFMA2(c04, a0, b4); FFMA2(c05, a0, b5);
            FFMA2(c06, a0, b6); FFMA2(c07, a0, b7);
            FFMA2(c10, a1, b0); FFMA2(c11, a1, b1);
            FFMA2(c12, a1, b2); FFMA2(c13, a1, b3);
            FFMA2(c14, a1, b4); FFMA2(c15, a1, b5);
            FFMA2(c16, a1, b6); FFMA2(c17, a1, b7);
            FFMA2(c20, a2, b0); FFMA2(c21, a2, b1);
            FFMA2(c22, a2, b2); FFMA2(c23, a2, b3);
            FFMA2(c24, a2, b4); FFMA2(c25, a2, b5);
            FFMA2(c26, a2, b6); FFMA2(c27, a2, b7);
            FFMA2(c30, a3, b0); FFMA2(c31, a3, b1);
            FFMA2(c32, a3, b2); FFMA2(c33, a3, b3);
            FFMA2(c34, a3, b4); FFMA2(c35, a3, b5);
            FFMA2(c36, a3, b6); FFMA2(c37, a3, b7);
        }

        if (c + 1 < NC) {
            const int nb = (c + 1) & 1;
            As[nb][akq0 + 0][arow0] = ra0.x; As[nb][akq0 + 1][arow0] = ra0.y;
            As[nb][akq0 + 2][arow0] = ra0.z; As[nb][akq0 + 3][arow0] = ra0.w;
            As[nb][akq1 + 0][arow1] = ra1.x; As[nb][akq1 + 1][arow1] = ra1.y;
            As[nb][akq1 + 2][arow1] = ra1.z; As[nb][akq1 + 3][arow1] = ra1.w;
            *reinterpret_cast<float4*>(&Bs[nb][brow0][bcol0]) = rb0;
            *reinterpret_cast<float4*>(&Bs[nb][brow1][bcol1]) = rb1;
        }
        __syncthreads();
    }

    // Epilogue: unpack row pairs, add bias, store.
    const float4 blo = *reinterpret_cast<const float4*>(&bias[n0 + tc * 4]);
    const float4 bhi = *reinterpret_cast<const float4*>(&bias[n0 + 64 + tc * 4]);

    #define EPI_PAIR(CA, CB, CC_, CD, CE, CF, CG, CH, IP) do { \
        float l0, h0, l1, h1, l2, h2, l3, h3; \
        float l4, h4, l5, h5, l6, h6, l7, h7; \
        unpack2(CA, l0, h0); unpack2(CB, l1, h1); \
        unpack2(CC_, l2, h2); unpack2(CD, l3, h3); \
        unpack2(CE, l4, h4); unpack2(CF, l5, h5); \
        unpack2(CG, l6, h6); unpack2(CH, l7, h7); \
        const int mA = m0 + tr * 8 + 2 * (IP); \
        float4 olo, ohi; \
        olo.x = l0 + blo.x; olo.y = l1 + blo.y; olo.z = l2 + blo.z; olo.w = l3 + blo.w; \
        ohi.x = l4 + bhi.x; ohi.y = l5 + bhi.y; ohi.z = l6 + bhi.z; ohi.w = l7 + bhi.w; \
        *reinterpret_cast<float4*>(&Cc[(size_t)mA * N + n0 + tc * 4]) = olo; \
        *reinterpret_cast<float4*>(&Cc[(size_t)mA * N + n0 + 64 + tc * 4]) = ohi; \
        olo.x = h0 + blo.x; olo.y = h1 + blo.y; olo.z = h2 + blo.z; olo.w = h3 + blo.w; \
        ohi.x = h4 + bhi.x; ohi.y = h5 + bhi.y; ohi.z = h6 + bhi.z; ohi.w = h7 + bhi.w; \
        *reinterpret_cast<float4*>(&Cc[(size_t)(mA + 1) * N + n0 + tc * 4]) = olo; \
        *reinterpret_cast<float4*>(&Cc[(size_t)(mA + 1) * N + n0 + 64 + tc * 4]) = ohi; \
    } while (0)

    EPI_PAIR(c00, c01, c02, c03, c04, c05, c06, c07, 0);
    EPI_PAIR(c10, c11, c12, c13, c14, c15, c16, c17, 1);
    EPI_PAIR(c20, c21, c22, c23, c24, c25, c26, c27, 2);
    EPI_PAIR(c30, c31, c32, c33, c34, c35, c36, c37, 3);
    #undef EPI_PAIR
}

__global__ void __launch_bounds__(256)
qkv_gemm_kernel(const float* __restrict__ x, const float* __restrict__ W,
                const float* __restrict__ bias)
{
    sgemm_core(x, W, bias, g_qkv, MTOT, 3 * Cx, Cx);
}

__global__ void __launch_bounds__(256)
out_gemm_kernel(const float* __restrict__ W, const float* __restrict__ bias,
                float* __restrict__ out)
{
    sgemm_core(g_attn, W, bias, out, MTOT, Cx, Cx);
}

// ---------------------------------------------------------------------------
// RMS norm + RoPE (in place on q,k). One warp per (token, head). [unchanged]
// ---------------------------------------------------------------------------
__global__ void norm_rope_kernel(const float* __restrict__ cosv,
                                 const float* __restrict__ sinv,
                                 const float* __restrict__ gq,
                                 const float* __restrict__ gk)
{
    const int warp = (blockIdx.x * blockDim.x + threadIdx.x) >> 5;
    const int lane = threadIdx.x & 31;
    const int m = warp >> 4;
    const int h = warp & 15;

    const float c = cosv[m * 32 + lane];
    const float s = sinv[m * 32 + lane];

    #pragma unroll
    for (int part = 0; part < 2; ++part) {
        float* ptr = &g_qkv[(size_t)m * 3072 + part * 1024 + h * 64];
        const float* gamma = (part == 0) ? gq : gk;
        float2 v = *reinterpret_cast<float2*>(ptr + 2 * lane);
        float ss = v.x * v.x + v.y * v.y;
        #pragma unroll
        for (int o = 16; o; o >>= 1) ss += __shfl_xor_sync(0xffffffffu, ss, o);
        const float inv = 8.0f / fmaxf(sqrtf(ss), 1e-12f);
        const float re = v.x * inv * gamma[h * 64 + 2 * lane];
        const float im = v.y * inv * gamma[h * 64 + 2 * lane + 1];
        float2 o2;
        o2.x = re * c - im * s;
        o2.y = re * s + im * c;
        *reinterpret_cast<float2*>(ptr + 2 * lane) = o2;
    }
}

// ===========================================================================
// Fused flash attention v3 [round-12 measured best, byte-identical].
// ===========================================================================
#define FL_QS (128 * 68)
#define FL_KS (64 * 70)
#define FL_VS (64 * 68)
#define FL_PS (128 * 68)
#define FL_SMEM_BYTES ((FL_QS + FL_KS + FL_VS + FL_PS) * 4)

__global__ void __launch_bounds__(256)
flash_attn_kernel()
{
    extern __shared__ float fsm[];
    float* Qs = fsm;
    float* Ks = fsm + FL_QS;
    float* Vs = Ks + FL_KS;
    float* Ps = Vs + FL_VS;

    const int bh = blockIdx.y;
    const int b = bh >> 4, h = bh & 15;
    const int l0 = blockIdx.x * 128;
    const int tid = threadIdx.x;
    const int tr = tid >> 4;
    const int tc = tid & 15;

    #pragma unroll
    for (int i = 0; i < 8; ++i) {
        const int e = tid + i * 256;
        const int row = e >> 4, c4 = (e & 15) * 4;
        float4 q = *reinterpret_cast<const float4*>(
            &g_qkv[(size_t)(b * Lx + l0 + row) * 3072 + h * 64 + c4]);
        q.x *= 0.125f; q.y *= 0.125f; q.z *= 0.125f; q.w *= 0.125f;
        *reinterpret_cast<float4*>(&Qs[row * 68 + c4]) = q;
    }

    float o[8][4];
    float lrow[8];
    #pragma unroll
    for (int i = 0; i < 8; ++i) {
        lrow[i] = 0.f;
        #pragma unroll
        for (int j = 0; j < 4; ++j) o[i][j] = 0.f;
    }

    for (int kb = 0; kb < Lx / 64; ++kb) {
        __syncthreads();
        #pragma unroll
        for (int i = 0; i < 4; ++i) {
            const int e = tid + i * 256;
            const int row = e >> 4, c4 = (e & 15) * 4;
            const float* base = &g_qkv[(size_t)(b * Lx + kb * 64 + row) * 3072 + h * 64 + c4];
            float4 kv = *reinterpret_cast<const float4*>(base + 1024);
            float2 k0; k0.x = kv.x; k0.y = kv.y;
            float2 k1; k1.x = kv.z; k1.y = kv.w;
            *reinterpret_cast<float2*>(&Ks[row * 70 + c4]) = k0;
            *reinterpret_cast<float2*>(&Ks[row * 70 + c4 + 2]) = k1;
            float4 vv = *reinterpret_cast<const float4*>(base + 2048);
            *reinterpret_cast<float4*>(&Vs[row * 68 + c4]) = vv;
        }
        __syncthreads();

        float s[8][4];
        #pragma unroll
        for (int i = 0; i < 8; ++i)
            #pragma unroll
            for (int j = 0; j < 4; ++j) s[i][j] = 0.f;

        #pragma unroll
        for (int d = 0; d < 64; d += 4) {
            float a[8][4];
            #pragma unroll
            for (int i = 0; i < 8; ++i) {
                float4 av = *reinterpret_cast<const float4*>(&Qs[(tr * 8 + i) * 68 + d]);
                a[i][0] = av.x; a[i][1] = av.y; a[i][2] = av.z; a[i][3] = av.w;
            }
            #pragma unroll
            for (int j = 0; j < 4; ++j) {
                float2 b0 = *reinterpret_cast<const float2*>(&Ks[(tc * 4 + j) * 70 + d]);
                float2 b1 = *reinterpret_cast<const float2*>(&Ks[(tc * 4 + j) * 70 + d + 2]);
                #pragma unroll
                for (int i = 0; i < 8; ++i)
                    s[i][j] += a[i][0] * b0.x + a[i][1] * b0.y
                             + a[i][2] * b1.x + a[i][3] * b1.y;
            }
        }

        #pragma unroll
        for (int i = 0; i < 8; ++i) {
            const float p0 = __expf(s[i][0] - 8.0f);
            const float p1 = __expf(s[i][1] - 8.0f);
            const float p2 = __expf(s[i][2] - 8.0f);
            const float p3 = __expf(s[i][3] - 8.0f);
            lrow[i] += (p0 + p1) + (p2 + p3);
            float4 pv; pv.x = p0; pv.y = p1; pv.z = p2; pv.w = p3;
            *reinterpret_cast<float4*>(&Ps[(tr * 8 + i) * 68 + tc * 4]) = pv;
        }
        __syncthreads();

        #pragma unroll
        for (int k = 0; k < 64; k += 4) {
            float a[8][4];
            #pragma unroll
            for (int i = 0; i < 8; ++i) {
                float4 av = *reinterpret_cast<const float4*>(&Ps[(tr * 8 + i) * 68 + k]);
                a[i][0] = av.x; a[i][1] = av.y; a[i][2] = av.z; a[i][3] = av.w;
            }
            #pragma unroll
            for (int kk = 0; kk < 4; ++kk) {
                float4 bv = *reinterpret_cast<const float4*>(&Vs[(k + kk) * 68 + tc * 4]);
                #pragma unroll
                for (int i = 0; i < 8; ++i) {
                    o[i][0] += a[i][kk] * bv.x;
                    o[i][1] += a[i][kk] * bv.y;
                    o[i][2] += a[i][kk] * bv.z;
                    o[i][3] += a[i][kk] * bv.w;
                }
            }
        }
    }

    #pragma unroll
    for (int i = 0; i < 8; ++i) {
        float l = lrow[i];
        l += __shfl_xor_sync(0xffffffffu, l, 8, 16);
        l += __shfl_xor_sync(0xffffffffu, l, 4, 16);
        l += __shfl_xor_sync(0xffffffffu, l, 2, 16);
        l += __shfl_xor_sync(0xffffffffu, l, 1, 16);
        const float inv = 1.0f / l;
        float4 ov;
        ov.x = o[i][0] * inv; ov.y = o[i][1] * inv;
        ov.z = o[i][2] * inv; ov.w = o[i][3] * inv;
        *reinterpret_cast<float4*>(
            &g_attn[(size_t)(b * Lx + l0 + tr * 8 + i) * 1024 + h * 64 + tc * 4]) = ov;
    }
}

// ---------------------------------------------------------------------------
extern "C" void kernel_launch(void* const* d_in, const int* in_sizes, int n_in,
                              void* d_out, int out_size)
{
    const float* x    = (const float*)d_in[0];
    const float* pcos = (const float*)d_in[1];
    const float* psin = (const float*)d_in[2];
    const float* Wqkv = (const float*)d_in[3];
    const float* bqkv = (const float*)d_in[4];
    const float* gq   = (const float*)d_in[5];
    const float* gk   = (const float*)d_in[6];
    const float* Wout = (const float*)d_in[7];
    const float* bout = (const float*)d_in[8];
    float* out = (float*)d_out;

    cudaFuncSetAttribute(flash_attn_kernel,
                         cudaFuncAttributeMaxDynamicSharedMemorySize, FL_SMEM_BYTES);

    // 1. QKV GEMM + bias -> g_qkv  (f32x2 packed FMA)
    qkv_gemm_kernel<<<dim3(3 * Cx / 128, MTOT / 128), 256>>>(x, Wqkv, bqkv);
    // 2. RMS norm + RoPE in place on q,k
    norm_rope_kernel<<<(MTOT * Hx) / 8, 256>>>(pcos, psin, gq, gk);
    // 3. Fused flash attention -> g_attn
    flash_attn_kernel<<<dim3(Lx / 128, Bx * Hx), 256, FL_SMEM_BYTES>>>();
    // 4. Out GEMM + bias -> d_out  (f32x2 packed FMA)
    out_gemm_kernel<<<dim3(Cx / 128, MTOT / 128), 256>>>(Wout, bout, out);
}